// round 12
// baseline (speedup 1.0000x reference)
#include <cuda_runtime.h>
#include <cstdint>

// ---------------------------------------------------------------------------
// PestDetectionSNN: two-layer LIF SNN.
//   Pass 0: W1 -> tf32 hi/lo, frag-ready interleaved layout in global (1 MB)
//   Pass 1: Z = event @ W1 via 3xTF32 mma.sync GEMM (hihi+lohi+hilo, fp32
//           accumulate, fold every 256 k) — MMA sequence bit-identical to R11
//   Pass 2: per-batch LIF scans + spike dots + classifier scan (R10 version)
//
// R12 perf changes (R11 was issue/smem-bound, not tensor-bound):
//  - smem layout [k8][row][hi_l4,lo_l4,hi_l4+4,lo_l4+4]: one LDS.128 per
//    fragment (hi+lo together) -> 64 scalar LDS/warp/kb becomes 16 LDS.128
//  - W1 converted ONCE by a pre-kernel (R11 re-converted it 400x64 times
//    with bank-conflicted scalar stores)
//  - double-buffered smem, single __syncthreads per kb (was 2)
// ---------------------------------------------------------------------------

#define B_  256
#define T_  100
#define D_  1024
#define H_  128
#define C_  5
#define MT  (B_ * T_)          // 25600 GEMM rows
#define NKB 64                 // 16-k blocks

#define DECAY1 0.90483741803595952865f
#define DECAY2 0.95122942450071400910f

// Scratch: Z = x @ W1, [25600 x 128] fp32 (13.1 MB)
__device__ float g_Z[MT * H_];
// W1 pre-converted: per kb: [k8][n][l4] float4 = (hi_k, lo_k, hi_k+4, lo_k+4)
__device__ float g_W1p[NKB * 4096];   // 1 MB

// ---- tf32 split helper ----------------------------------------------------
__device__ __forceinline__ float to_tf32(float x) {
    unsigned r;
    asm("cvt.rna.tf32.f32 %0, %1;" : "=r"(r) : "r"(__float_as_uint(x)));
    return __uint_as_float(r);
}

// mma.sync m16n8k8 tf32, D += A*B (C==D registers)
#define MMA_TF32(d, a, b)                                                   \
    asm volatile(                                                           \
        "mma.sync.aligned.m16n8k8.row.col.f32.tf32.tf32.f32 "               \
        "{%0,%1,%2,%3}, {%4,%5,%6,%7}, {%8,%9}, {%0,%1,%2,%3};"             \
        : "+f"((d)[0]), "+f"((d)[1]), "+f"((d)[2]), "+f"((d)[3])            \
        : "r"((a)[0]), "r"((a)[1]), "r"((a)[2]), "r"((a)[3]),               \
          "r"((b)[0]), "r"((b)[1]))

// ---------------------------------------------------------------------------
// Pass 0: convert W1 to hi/lo frag-ready layout. 65536 threads.
// cell (kb, k8, n, l4): float4 at g_W1p[kb*4096 + k8*2048 + n*16 + l4*4]
//   = (hi(W1[k][n]), lo, hi(W1[k+4][n]), lo) with k = kb*16 + k8*8 + l4
// ---------------------------------------------------------------------------
__global__ __launch_bounds__(256) void w1_convert(const float* __restrict__ W1)
{
    const int c  = blockIdx.x * 256 + threadIdx.x;
    const int n  = c & 127;
    const int l4 = (c >> 7) & 3;
    const int k8 = (c >> 9) & 1;
    const int kb = c >> 10;
    const int k  = kb * 16 + k8 * 8 + l4;
    const float w0 = W1[k * H_ + n];
    const float w4 = W1[(k + 4) * H_ + n];
    const float h0 = to_tf32(w0), e0 = to_tf32(w0 - h0);
    const float h4 = to_tf32(w4), e4 = to_tf32(w4 - h4);
    *(float4*)&g_W1p[kb * 4096 + k8 * 2048 + n * 16 + l4 * 4] =
        make_float4(h0, e0, h4, e4);
}

// ---------------------------------------------------------------------------
// Pass 1: tensor-core GEMM. BM=64, BN=128(all H), BK=16, 256 thr (8 warps),
// warp grid 2(M) x 4(N), warp tile 32x32. Double-buffered, 1 sync/kb.
// ---------------------------------------------------------------------------
__global__ __launch_bounds__(256, 2) void snn_gemm_tc(const float* __restrict__ A)
{
    __shared__ __align__(16) float As[2][2048];   // [k8][row 0..63][16]
    __shared__ __align__(16) float Bs[2][4096];   // [k8][n 0..127][16]

    const int tid  = threadIdx.x;
    const int m0   = blockIdx.x * 64;
    const int lane = tid & 31;
    const int wid  = tid >> 5;
    const int g    = lane >> 2;     // 0..7
    const int l4   = lane & 3;      // 0..3
    const int wm   = wid >> 2;      // warp M 0..1
    const int wn   = wid & 3;       // warp N 0..3

    // A producer map: row am, k-cols akc..akc+3 (one float4)
    const int am   = tid >> 2;            // 0..63
    const int akc  = (tid & 3) << 2;      // 0,4,8,12
    const int kk8  = akc >> 3;            // k8 plane of this thread's elems
    const int half = (akc >> 2) & 1;      // 0: k in [0,4), 1: k in [4,8)
    const int astore = kk8 * 1024 + am * 16 + half * 2;

    const float*  Ap = A + (size_t)(m0 + am) * D_ + akc;
    const float4* Wp = (const float4*)g_W1p;

    // prefetch kb=0
    float4 a4  = *(const float4*)Ap;
    float4 bc0 = Wp[tid];
    float4 bc1 = Wp[tid + 256];
    float4 bc2 = Wp[tid + 512];
    float4 bc3 = Wp[tid + 768];

    // store kb=0 into buffer 0
    {
        float av[4] = {a4.x, a4.y, a4.z, a4.w};
#pragma unroll
        for (int i = 0; i < 4; i++) {
            float h = to_tf32(av[i]);
            float e = to_tf32(av[i] - h);
            *(float2*)&As[0][astore + i * 4] = make_float2(h, e);
        }
        float4* bf = (float4*)Bs[0];
        bf[tid] = bc0; bf[tid + 256] = bc1; bf[tid + 512] = bc2; bf[tid + 768] = bc3;
    }
    __syncthreads();

    float accT[2][4][4] = {};   // running totals
    float accB[2][4][4] = {};   // per-256k accumulators

    int buf = 0;
    for (int kb = 0; kb < NKB; kb++) {
        // prefetch next tile (hidden under MMA work)
        if (kb < NKB - 1) {
            a4 = *(const float4*)(Ap + (kb + 1) * 16);
            const float4* wp = Wp + (kb + 1) * 1024;
            bc0 = wp[tid]; bc1 = wp[tid + 256]; bc2 = wp[tid + 512]; bc3 = wp[tid + 768];
        }

        // ---- compute on current buffer ----
        const float* as = As[buf];
        const float* bs = Bs[buf];
#pragma unroll
        for (int k8 = 0; k8 < 2; k8++) {
            const int ab = k8 * 1024 + l4 * 4;
            const int bb = k8 * 2048 + l4 * 4;

            unsigned ah[2][4], al[2][4];
#pragma unroll
            for (int mi = 0; mi < 2; mi++) {
                const int r0 = wm * 32 + mi * 16 + g;
                float4 v0 = *(const float4*)&as[r0 * 16 + ab];
                float4 v1 = *(const float4*)&as[(r0 + 8) * 16 + ab];
                ah[mi][0] = __float_as_uint(v0.x); ah[mi][1] = __float_as_uint(v1.x);
                ah[mi][2] = __float_as_uint(v0.z); ah[mi][3] = __float_as_uint(v1.z);
                al[mi][0] = __float_as_uint(v0.y); al[mi][1] = __float_as_uint(v1.y);
                al[mi][2] = __float_as_uint(v0.w); al[mi][3] = __float_as_uint(v1.w);
            }
            unsigned bh[4][2], bl[4][2];
#pragma unroll
            for (int ni = 0; ni < 4; ni++) {
                const int nr = wn * 32 + ni * 8 + g;
                float4 v = *(const float4*)&bs[nr * 16 + bb];
                bh[ni][0] = __float_as_uint(v.x); bh[ni][1] = __float_as_uint(v.z);
                bl[ni][0] = __float_as_uint(v.y); bl[ni][1] = __float_as_uint(v.w);
            }
            // hi*hi
#pragma unroll
            for (int mi = 0; mi < 2; mi++)
#pragma unroll
                for (int ni = 0; ni < 4; ni++)
                    MMA_TF32(accB[mi][ni], ah[mi], bh[ni]);
            // lo*hi
#pragma unroll
            for (int mi = 0; mi < 2; mi++)
#pragma unroll
                for (int ni = 0; ni < 4; ni++)
                    MMA_TF32(accB[mi][ni], al[mi], bh[ni]);
            // hi*lo
#pragma unroll
            for (int mi = 0; mi < 2; mi++)
#pragma unroll
                for (int ni = 0; ni < 4; ni++)
                    MMA_TF32(accB[mi][ni], ah[mi], bl[ni]);
        }

        // 2-level fold every 16 kb (= 256 k) — same points as R11
        if ((kb & 15) == 15) {
#pragma unroll
            for (int mi = 0; mi < 2; mi++)
#pragma unroll
                for (int ni = 0; ni < 4; ni++)
#pragma unroll
                    for (int j = 0; j < 4; j++) {
                        accT[mi][ni][j] = __fadd_rn(accT[mi][ni][j], accB[mi][ni][j]);
                        accB[mi][ni][j] = 0.0f;
                    }
        }

        // ---- store next tile into other buffer, single sync ----
        if (kb < NKB - 1) {
            const int nb = buf ^ 1;
            float av[4] = {a4.x, a4.y, a4.z, a4.w};
#pragma unroll
            for (int i = 0; i < 4; i++) {
                float h = to_tf32(av[i]);
                float e = to_tf32(av[i] - h);
                *(float2*)&As[nb][astore + i * 4] = make_float2(h, e);
            }
            float4* bf = (float4*)Bs[nb];
            bf[tid] = bc0; bf[tid + 256] = bc1; bf[tid + 512] = bc2; bf[tid + 768] = bc3;
            __syncthreads();
            buf = nb;
        }
    }

    // ---- epilogue: write fragments to g_Z (same as R11) ----
#pragma unroll
    for (int mi = 0; mi < 2; mi++) {
        const int row0 = m0 + wm * 32 + mi * 16 + g;
#pragma unroll
        for (int ni = 0; ni < 4; ni++) {
            const int col = wn * 32 + ni * 8 + 2 * l4;
            *(float2*)&g_Z[(size_t)row0 * H_ + col] =
                make_float2(accT[mi][ni][0], accT[mi][ni][1]);
            *(float2*)&g_Z[(size_t)(row0 + 8) * H_ + col] =
                make_float2(accT[mi][ni][2], accT[mi][ni][3]);
        }
    }
}

// ---------------------------------------------------------------------------
// Pass 2: per-batch LIF scans (unchanged; 13.6us).
// ---------------------------------------------------------------------------
__global__ __launch_bounds__(128) void snn_scan_kernel(
    const float* __restrict__ b1, const float* __restrict__ W2,
    const float* __restrict__ b2, float* __restrict__ out)
{
    __shared__ unsigned s1w[T_ * 4];     // spike bitmasks: [t][warp]
    __shared__ float    W2s[H_ * C_];    // 640 floats
    __shared__ float    dd[T_ * C_];     // layer-2 drive per (t,c)

    const int b    = blockIdx.x;
    const int tid  = threadIdx.x;        // = h
    const int lane = tid & 31;
    const int warp = tid >> 5;

    for (int i = tid; i < H_ * C_; i += 128) W2s[i] = W2[i];

    // ---- phase 1: feature-layer LIF scan (chunked, MLP=20) ----
    const float b1h = b1[tid];
    const float* zp = g_Z + (size_t)b * T_ * H_ + tid;
    float v1 = 0.0f;

    float zbuf[20];
#pragma unroll
    for (int j = 0; j < 20; j++) zbuf[j] = zp[j * H_];

    for (int c = 0; c < 5; c++) {
        float znext[20];
        if (c < 4) {
#pragma unroll
            for (int j = 0; j < 20; j++)
                znext[j] = zp[(c * 20 + 20 + j) * H_];
        }
#pragma unroll
        for (int j = 0; j < 20; j++) {
            const int t = c * 20 + j;
            v1 = __fadd_rn(fmaf(v1, DECAY1, zbuf[j]), b1h);
            bool s = (v1 >= 1.0f);
            if (s) v1 = 0.0f;
            unsigned m = __ballot_sync(0xffffffffu, s);
            if (lane == 0) s1w[t * 4 + warp] = m;
        }
        if (c < 4) {
#pragma unroll
            for (int j = 0; j < 20; j++) zbuf[j] = znext[j];
        }
    }
    __syncthreads();

    // ---- phase 2: s1 @ W2 for all (t,c) ----
    for (int p = tid; p < T_ * C_; p += 128) {
        const int t = p / C_;
        const int c = p - t * C_;
        float sum = 0.0f;
#pragma unroll
        for (int w = 0; w < 4; w++) {
            const unsigned msk = s1w[t * 4 + w];
            const float* wp = &W2s[w * 32 * C_ + c];
#pragma unroll
            for (int bit = 0; bit < 32; bit++) {
                if (msk & (1u << bit)) sum = __fadd_rn(sum, wp[bit * C_]);
            }
        }
        dd[p] = sum;
    }
    __syncthreads();

    // ---- phase 3: classifier LIF scan ----
    if (tid < C_) {
        const float b2c = b2[tid];
        float v2 = 0.0f, acc = 0.0f;
        for (int t = 0; t < T_; t++) {
            v2 = __fadd_rn(fmaf(v2, DECAY2, dd[t * C_ + tid]), b2c);
            if (v2 >= 1.0f) { acc += 1.0f; v2 = 0.0f; }
        }
        out[b * C_ + tid] = acc / (float)T_;
    }
}

// ---------------------------------------------------------------------------
// kernel_launch
// inputs: event_stream[256,100,1024] f32, W1[1024,128], b1[128], W2[128,5], b2[5]
// output: [256,5] f32
// ---------------------------------------------------------------------------
extern "C" void kernel_launch(void* const* d_in, const int* in_sizes, int n_in,
                              void* d_out, int out_size)
{
    const float* ev = (const float*)d_in[0];
    const float* W1 = (const float*)d_in[1];
    const float* b1 = (const float*)d_in[2];
    const float* W2 = (const float*)d_in[3];
    const float* b2 = (const float*)d_in[4];
    float* out = (float*)d_out;

    w1_convert<<<256, 256>>>(W1);
    snn_gemm_tc<<<MT / 64, 256>>>(ev);
    snn_scan_kernel<<<B_, 128>>>(b1, W2, b2, out);
}